// round 12
// baseline (speedup 1.0000x reference)
#include <cuda_runtime.h>
#include <cuda_fp16.h>
#include <cstdint>

#define N_NODES_C 100000
#define D_C 64
#define ROWS_PER_WARP 8

typedef unsigned long long ull;

// Y = X @ W in fp16, plus one extra all-zero row (index N_NODES_C) used as a
// safe target for out-of-range edge slots in K2 (predicate-free inner loop).
__device__ __half g_Yh[(size_t)(N_NODES_C + 1) * D_C];

// ---------------------------------------------------------------------------
// helpers
// ---------------------------------------------------------------------------
__device__ __forceinline__ ull pack2(float x, float y) {
    ull r; asm("mov.b64 %0, {%1, %2};" : "=l"(r) : "f"(x), "f"(y)); return r;
}
__device__ __forceinline__ void unpack2(ull v, float& x, float& y) {
    asm("mov.b64 {%0, %1}, %2;" : "=f"(x), "=f"(y) : "l"(v));
}
__device__ __forceinline__ ull fadd2(ull a, ull b) {
    ull d; asm("add.rn.f32x2 %0, %1, %2;" : "=l"(d) : "l"(a), "l"(b));
    return d;
}
__device__ __forceinline__ uint32_t f2tf32(float f) {
    uint32_t r; asm("cvt.rna.tf32.f32 %0, %1;" : "=r"(r) : "f"(f)); return r;
}
__device__ __forceinline__ void mma_tf32(float* d,
                                         uint32_t a0, uint32_t a1, uint32_t a2, uint32_t a3,
                                         uint32_t b0, uint32_t b1) {
    asm volatile(
        "mma.sync.aligned.m16n8k8.row.col.f32.tf32.tf32.f32 "
        "{%0,%1,%2,%3}, {%4,%5,%6,%7}, {%8,%9}, {%0,%1,%2,%3};"
        : "+f"(d[0]), "+f"(d[1]), "+f"(d[2]), "+f"(d[3])
        : "r"(a0), "r"(a1), "r"(a2), "r"(a3), "r"(b0), "r"(b1));
}

// ---------------------------------------------------------------------------
// K1: Y[M,64] = X[M,64] @ W[64,64] via tf32 tensor-core MMA, fp16 output.
// (unchanged — measured ~9.2us, at its memory floor)
// ---------------------------------------------------------------------------
#define XPAD 68
#define WPAD 72
#define SMEM_GEMM ((128 * XPAD + 64 * WPAD) * 4)   // 53,248 B

__global__ __launch_bounds__(256)
void gemm_tf32(const float* __restrict__ X,
               const float* __restrict__ W,
               __half* __restrict__ Y,
               int M)
{
    extern __shared__ uint32_t sm4[];
    uint32_t* xs = sm4;                 // [128][XPAD] tf32 bits
    uint32_t* ws = sm4 + 128 * XPAD;    // [64][WPAD]  tf32 bits

    const int t  = threadIdx.x;
    const int m0 = blockIdx.x * 128;

    #pragma unroll
    for (int i = 0; i < 16; i++) {
        int idx = t + i * 256;              // k*64 + n
        int k = idx >> 6, n = idx & 63;
        ws[k * WPAD + n] = f2tf32(W[idx]);
    }

    #pragma unroll
    for (int i = 0; i < 8; i++) {
        int idx = t + i * 256;              // float4 index
        int m  = idx >> 4;
        int c4 = idx & 15;
        float4 v = make_float4(0.f, 0.f, 0.f, 0.f);
        if (m0 + m < M)
            v = ((const float4*)X)[(size_t)(m0 + m) * 16 + c4];
        uint32_t* p = xs + m * XPAD + c4 * 4;
        p[0] = f2tf32(v.x); p[1] = f2tf32(v.y);
        p[2] = f2tf32(v.z); p[3] = f2tf32(v.w);
    }
    __syncthreads();

    const int warp = t >> 5;
    const int lane = t & 31;
    const int g  = lane >> 2;
    const int tg = lane & 3;
    const int mrow = warp * 16;

    float acc[8][4];
    #pragma unroll
    for (int j = 0; j < 8; j++)
        #pragma unroll
        for (int c = 0; c < 4; c++) acc[j][c] = 0.f;

    #pragma unroll
    for (int ks = 0; ks < 8; ks++) {
        const int k0 = ks * 8;
        uint32_t a0 = xs[(mrow + g)     * XPAD + k0 + tg];
        uint32_t a1 = xs[(mrow + g + 8) * XPAD + k0 + tg];
        uint32_t a2 = xs[(mrow + g)     * XPAD + k0 + tg + 4];
        uint32_t a3 = xs[(mrow + g + 8) * XPAD + k0 + tg + 4];
        #pragma unroll
        for (int j = 0; j < 8; j++) {
            uint32_t b0 = ws[(k0 + tg)     * WPAD + j * 8 + g];
            uint32_t b1 = ws[(k0 + tg + 4) * WPAD + j * 8 + g];
            mma_tf32(acc[j], a0, a1, a2, a3, b0, b1);
        }
    }

    const int r0 = m0 + mrow + g;
    const int r1 = r0 + 8;
    #pragma unroll
    for (int j = 0; j < 8; j++) {
        int col = j * 8 + 2 * tg;
        __half2 lo = __floats2half2_rn(acc[j][0], acc[j][1]);
        __half2 hi = __floats2half2_rn(acc[j][2], acc[j][3]);
        if (r0 <= M) *(__half2*)(Y + (size_t)r0 * 64 + col) = lo;
        if (r1 <= M) *(__half2*)(Y + (size_t)r1 * 64 + col) = hi;
    }
}

// ---------------------------------------------------------------------------
// K2 v7: out[i] = sum_{e in [rp[i],rp[i+1])} Yh[ci[e]]   (fp32 accumulation)
// Same pipeline structure as v6b (rows-per-warp=8, prefetch next row's
// indices, pipelined continuation windows, warp-uniform half-window path).
// Change: __launch_bounds__(128, 12) caps regs at 42 -> 48 warps/SM resident
// (was reg-capped at 42 warps by 48 regs/thread). Latency-bound kernel; more
// resident warps is the direct lever.
// ---------------------------------------------------------------------------
struct Idx4 { int c0, c1, c2, c3; };

__device__ __forceinline__ Idx4 load_idx4(const int* __restrict__ ci,
                                          int k, int e, int g, int nem1)
{
    Idx4 r;
    int i0 = k + g, i1 = k + g + 4, i2 = k + g + 8, i3 = k + g + 12;
    r.c0 = __ldg(ci + min(i0, nem1)); r.c0 = (i0 < e) ? r.c0 : N_NODES_C;
    r.c1 = __ldg(ci + min(i1, nem1)); r.c1 = (i1 < e) ? r.c1 : N_NODES_C;
    r.c2 = __ldg(ci + min(i2, nem1)); r.c2 = (i2 < e) ? r.c2 : N_NODES_C;
    r.c3 = __ldg(ci + min(i3, nem1)); r.c3 = (i3 < e) ? r.c3 : N_NODES_C;
    return r;
}

__device__ __forceinline__ void consume_full(ull* acc2, uint4 v0, uint4 v1,
                                             uint4 v2, uint4 v3)
{
    const __half2* h0 = (const __half2*)&v0;
    const __half2* h1 = (const __half2*)&v1;
    const __half2* h2 = (const __half2*)&v2;
    const __half2* h3 = (const __half2*)&v3;
    #pragma unroll
    for (int i = 0; i < 4; i++) {
        __half2 s01 = __hadd2(h0[i], h1[i]);
        __half2 s23 = __hadd2(h2[i], h3[i]);
        __half2 sall = __hadd2(s01, s23);
        float2 f = __half22float2(sall);
        acc2[i] = fadd2(acc2[i], pack2(f.x, f.y));
    }
}

__device__ __forceinline__ void consume_half(ull* acc2, uint4 v0, uint4 v1)
{
    const __half2* h0 = (const __half2*)&v0;
    const __half2* h1 = (const __half2*)&v1;
    #pragma unroll
    for (int i = 0; i < 4; i++) {
        __half2 s01 = __hadd2(h0[i], h1[i]);
        float2 f = __half22float2(s01);
        acc2[i] = fadd2(acc2[i], pack2(f.x, f.y));
    }
}

__global__ __launch_bounds__(128, 12)
void spmm_agg_v7(const __half* __restrict__ Y,
                 const int* __restrict__ rp,
                 const int* __restrict__ ci,
                 float* __restrict__ out,
                 int n_edges)
{
    const int warp_g = (blockIdx.x * blockDim.x + threadIdx.x) >> 5;
    const int lane = threadIdx.x & 31;
    const int g   = lane >> 3;     // edge subgroup 0..3
    const int sub = lane & 7;      // 16B chunk of the 128B fp16 row
    const int base_row = warp_g * ROWS_PER_WARP;
    if (base_row >= N_NODES_C) return;

    const int nem1 = n_edges - 1;
    const uint4* __restrict__ baseY = (const uint4*)Y;

    // One coalesced load of 9 row pointers for this warp's rows.
    int rpv = __ldg(rp + base_row + min(lane, ROWS_PER_WARP));

    // Pipeline prologue: row 0 bounds + window-0 indices.
    int s = __shfl_sync(0xffffffffu, rpv, 0);
    int e = __shfl_sync(0xffffffffu, rpv, 1);
    Idx4 c = load_idx4(ci, s, e, g, nem1);

    #pragma unroll
    for (int j = 0; j < ROWS_PER_WARP; j++) {
        const int s_cur = s, e_cur = e;
        const int n = e_cur - s_cur;

        ull acc2[4] = {0ull, 0ull, 0ull, 0ull};

        // Window 0: issue gathers (indices already in flight/ready).
        // Warp-uniform: skip upper half if n <= 8.
        const bool big0 = (n > 8);
        uint4 v0 = __ldg(baseY + (size_t)c.c0 * 8 + sub);
        uint4 v1 = __ldg(baseY + (size_t)c.c1 * 8 + sub);
        uint4 v2 = make_uint4(0u, 0u, 0u, 0u);
        uint4 v3 = make_uint4(0u, 0u, 0u, 0u);
        if (big0) {
            v2 = __ldg(baseY + (size_t)c.c2 * 8 + sub);
            v3 = __ldg(baseY + (size_t)c.c3 * 8 + sub);
        }

        // Prefetch next row's bounds + window-0 indices while gathers fly.
        Idx4 nc = { N_NODES_C, N_NODES_C, N_NODES_C, N_NODES_C };
        if (j + 1 < ROWS_PER_WARP) {
            s = __shfl_sync(0xffffffffu, rpv, j + 1);
            e = __shfl_sync(0xffffffffu, rpv, j + 2);
            nc = load_idx4(ci, s, e, g, nem1);
        }

        // Prefetch continuation window-1 indices if needed (n > 16).
        int k = s_cur + 16;
        Idx4 cc = { N_NODES_C, N_NODES_C, N_NODES_C, N_NODES_C };
        if (k < e_cur) cc = load_idx4(ci, k, e_cur, g, nem1);

        // Consume window 0.
        if (big0) consume_full(acc2, v0, v1, v2, v3);
        else      consume_half(acc2, v0, v1);

        // Continuation windows (pipelined: next window's idx loaded before
        // consuming the current one).
        while (k < e_cur) {
            const int rem = e_cur - k;
            const bool big = (rem > 8);
            uint4 w0 = __ldg(baseY + (size_t)cc.c0 * 8 + sub);
            uint4 w1 = __ldg(baseY + (size_t)cc.c1 * 8 + sub);
            uint4 w2 = make_uint4(0u, 0u, 0u, 0u);
            uint4 w3 = make_uint4(0u, 0u, 0u, 0u);
            if (big) {
                w2 = __ldg(baseY + (size_t)cc.c2 * 8 + sub);
                w3 = __ldg(baseY + (size_t)cc.c3 * 8 + sub);
            }
            const int k2 = k + 16;
            if (k2 < e_cur) cc = load_idx4(ci, k2, e_cur, g, nem1);
            if (big) consume_full(acc2, w0, w1, w2, w3);
            else     consume_half(acc2, w0, w1);
            k = k2;
        }

        // Reduce the 4 edge subgroups and store row.
        float a[8];
        #pragma unroll
        for (int i = 0; i < 4; i++) unpack2(acc2[i], a[2 * i], a[2 * i + 1]);
        #pragma unroll
        for (int q = 0; q < 8; q++) {
            a[q] += __shfl_xor_sync(0xffffffffu, a[q], 8);
            a[q] += __shfl_xor_sync(0xffffffffu, a[q], 16);
        }
        if (lane < 8) {
            float* op = out + (size_t)(base_row + j) * 64 + sub * 8;
            *(float4*)(op + 0) = make_float4(a[0], a[1], a[2], a[3]);
            *(float4*)(op + 4) = make_float4(a[4], a[5], a[6], a[7]);
        }

        c = nc;
    }
}

// ---------------------------------------------------------------------------
// kernel_launch
// Inputs: 0=X [100000,64] f32, 1=weights [64,64] f32, 2=row_pointers [100001] i32,
//         3=column_index [1600000] i32, 4..6 unused metadata.
// ---------------------------------------------------------------------------
extern "C" void kernel_launch(void* const* d_in, const int* in_sizes, int n_in,
                              void* d_out, int out_size)
{
    const float* X  = (const float*)d_in[0];
    const float* W  = (const float*)d_in[1];
    const int*   rp = (const int*)d_in[2];
    const int*   ci = (const int*)d_in[3];
    float*       out = (float*)d_out;

    const int M = in_sizes[0] / D_C;       // 100000
    const int NE = in_sizes[3];            // 1600000

    __half* Y;
    cudaGetSymbolAddress((void**)&Y, g_Yh);

    cudaFuncSetAttribute(gemm_tf32, cudaFuncAttributeMaxDynamicSharedMemorySize, SMEM_GEMM);
    {
        // grid covers rows 0..M inclusive (row M is the zero row)
        dim3 grid((M + 128) / 128);
        gemm_tf32<<<grid, 256, SMEM_GEMM>>>(X, W, Y, M);
    }
    {
        const int n_warps  = (M + ROWS_PER_WARP - 1) / ROWS_PER_WARP;   // 12500
        const int n_blocks = (n_warps + 3) / 4;                         // 3125
        spmm_agg_v7<<<n_blocks, 128>>>(Y, rp, ci, out, NE);
    }
}